// round 2
// baseline (speedup 1.0000x reference)
#include <cuda_runtime.h>
#include <math.h>

#define NWIN   1024
#define NT     64
#define DIMF   384
#define NHEADS 12
#define HDIM   32
#define MTOK   (NWIN * NT)          // 65536
#define QKVCOLS (3 * DIMF)          // 1152
#define MAX_LOGIT 4.605170185988091f // ln(100)

// Scratch (device globals: allocation-free per harness rules)
__device__ float g_qkv[(size_t)MTOK * QKVCOLS];   // ~302 MB
__device__ float g_ctx[(size_t)MTOK * DIMF];      // ~100 MB
__device__ float g_bias[NHEADS * NT * NT];        // 16*sigmoid(rpb), per head

// ---------------------------------------------------------------------------
// K0: continuous position bias MLP (225x2 -> 512 relu -> 12) + gather + sigmoid
// ---------------------------------------------------------------------------
__global__ void rpb_kernel(const float* __restrict__ table,
                           const float* __restrict__ w1,
                           const float* __restrict__ b1,
                           const float* __restrict__ w2,
                           const float* __restrict__ b2,
                           const int*   __restrict__ idx)
{
    __shared__ float s_w1[1024];
    __shared__ float s_b1[512];
    __shared__ float s_w2[512 * 12];
    __shared__ float s_b2[12];
    __shared__ float s_rpb[225 * 12];
    int tid = threadIdx.x;

    for (int i = tid; i < 1024; i += 256) s_w1[i] = w1[i];
    for (int i = tid; i < 512;  i += 256) s_b1[i] = b1[i];
    for (int i = tid; i < 6144; i += 256) s_w2[i] = w2[i];
    if (tid < 12) s_b2[tid] = b2[tid];
    __syncthreads();

    if (tid < 225) {
        float t0 = table[tid * 2 + 0];
        float t1 = table[tid * 2 + 1];
        float acc[12];
        #pragma unroll
        for (int h = 0; h < 12; h++) acc[h] = s_b2[h];
        for (int j = 0; j < 512; j++) {
            float hj = fmaf(t0, s_w1[j], fmaf(t1, s_w1[512 + j], s_b1[j]));
            hj = fmaxf(hj, 0.0f);
            #pragma unroll
            for (int h = 0; h < 12; h++)
                acc[h] = fmaf(hj, s_w2[j * 12 + h], acc[h]);
        }
        #pragma unroll
        for (int h = 0; h < 12; h++) s_rpb[tid * 12 + h] = acc[h];
    }
    __syncthreads();

    for (int o = tid; o < NHEADS * NT * NT; o += 256) {
        int h = o >> 12;          // o / 4096
        int p = o & 4095;         // (i*64 + j)
        float r = s_rpb[idx[p] * 12 + h];
        g_bias[o] = 16.0f / (1.0f + expf(-r));
    }
}

// ---------------------------------------------------------------------------
// Tiled SGEMM: C[M,N] = A[M,K] @ B[K,N] (+ bias[N]).  BM=BN=128, BK=8, 8x8/thr
// Requires M%128==0, N%128==0, K%8==0 (true for both call sites).
// ---------------------------------------------------------------------------
__global__ __launch_bounds__(256) void sgemm128(
    const float* __restrict__ A, const float* __restrict__ B,
    const float* __restrict__ bias, float* __restrict__ C,
    int M, int N, int K)
{
    __shared__ float As[8][128];
    __shared__ float Bs[8][128];

    const int tid = threadIdx.x;
    const int bx = blockIdx.x;   // N tile
    const int by = blockIdx.y;   // M tile
    const int tx = tid & 15;     // 16 across N
    const int ty = tid >> 4;     // 16 down M

    float acc[8][8];
    #pragma unroll
    for (int i = 0; i < 8; i++)
        #pragma unroll
        for (int j = 0; j < 8; j++) acc[i][j] = 0.0f;

    const int a_row = tid >> 1;          // 0..127
    const int a_col = (tid & 1) * 4;     // 0 or 4
    const int b_row = tid >> 5;          // 0..7
    const int b_col = (tid & 31) * 4;    // 0..124

    const float* Ap = A + (size_t)(by * 128 + a_row) * K + a_col;
    const float* Bp = B + (size_t)b_row * N + bx * 128 + b_col;

    for (int k0 = 0; k0 < K; k0 += 8) {
        float4 av = *(const float4*)(Ap + k0);
        As[a_col + 0][a_row] = av.x;
        As[a_col + 1][a_row] = av.y;
        As[a_col + 2][a_row] = av.z;
        As[a_col + 3][a_row] = av.w;
        float4 bv = *(const float4*)(Bp + (size_t)k0 * N);
        *(float4*)&Bs[b_row][b_col] = bv;
        __syncthreads();

        #pragma unroll
        for (int k = 0; k < 8; k++) {
            float4 a0 = *(const float4*)&As[k][ty * 8];
            float4 a1 = *(const float4*)&As[k][ty * 8 + 4];
            float4 b0 = *(const float4*)&Bs[k][tx * 8];
            float4 b1 = *(const float4*)&Bs[k][tx * 8 + 4];
            float ar[8] = {a0.x, a0.y, a0.z, a0.w, a1.x, a1.y, a1.z, a1.w};
            float br[8] = {b0.x, b0.y, b0.z, b0.w, b1.x, b1.y, b1.z, b1.w};
            #pragma unroll
            for (int i = 0; i < 8; i++)
                #pragma unroll
                for (int j = 0; j < 8; j++)
                    acc[i][j] = fmaf(ar[i], br[j], acc[i][j]);
        }
        __syncthreads();
    }

    float bvals[8];
    if (bias) {
        const float* bp = bias + bx * 128 + tx * 8;
        #pragma unroll
        for (int j = 0; j < 8; j++) bvals[j] = bp[j];
    } else {
        #pragma unroll
        for (int j = 0; j < 8; j++) bvals[j] = 0.0f;
    }

    #pragma unroll
    for (int i = 0; i < 8; i++) {
        size_t row = (size_t)(by * 128 + ty * 8 + i);
        float* Cp = C + row * N + bx * 128 + tx * 8;
        float4 v0 = make_float4(acc[i][0] + bvals[0], acc[i][1] + bvals[1],
                                acc[i][2] + bvals[2], acc[i][3] + bvals[3]);
        float4 v1 = make_float4(acc[i][4] + bvals[4], acc[i][5] + bvals[5],
                                acc[i][6] + bvals[6], acc[i][7] + bvals[7]);
        *(float4*)(Cp)     = v0;
        *(float4*)(Cp + 4) = v1;
    }
}

// ---------------------------------------------------------------------------
// K2: per (head, window) cosine attention. 128 threads.
// ---------------------------------------------------------------------------
__global__ __launch_bounds__(128) void attn_kernel(
    const float* __restrict__ mask, const float* __restrict__ logit_scale)
{
    const int h   = blockIdx.x;
    const int b   = blockIdx.y;
    const int tid = threadIdx.x;

    __shared__ float sq[64][33];
    __shared__ float sk[64][33];
    __shared__ float sv[64][33];
    __shared__ float sa[64][65];
    __shared__ float s_scale;

    const float* qkv = g_qkv + (size_t)b * 64 * QKVCOLS + h * 32;

    // load q,k,v tiles (each 64x32) via float4
    for (int i = tid; i < 512; i += 128) {
        int row = i >> 3;
        int f   = (i & 7) * 4;
        const float* base = qkv + (size_t)row * QKVCOLS + f;
        float4 v;
        v = *(const float4*)(base);
        sq[row][f] = v.x; sq[row][f + 1] = v.y; sq[row][f + 2] = v.z; sq[row][f + 3] = v.w;
        v = *(const float4*)(base + 384);
        sk[row][f] = v.x; sk[row][f + 1] = v.y; sk[row][f + 2] = v.z; sk[row][f + 3] = v.w;
        v = *(const float4*)(base + 768);
        sv[row][f] = v.x; sv[row][f + 1] = v.y; sv[row][f + 2] = v.z; sv[row][f + 3] = v.w;
    }
    if (tid == 0) s_scale = expf(fminf(logit_scale[h], MAX_LOGIT));
    __syncthreads();

    // row-normalize q (threads 0..63, with logit scale folded in) and k (64..127)
    {
        int r = tid & 63;
        float (*mat)[33] = (tid < 64) ? sq : sk;
        float ss = 0.0f;
        #pragma unroll
        for (int i = 0; i < 32; i++) { float v = mat[r][i]; ss = fmaf(v, v, ss); }
        float sc = rsqrtf(fmaxf(ss, 1e-12f));
        if (tid < 64) sc *= s_scale;
        #pragma unroll
        for (int i = 0; i < 32; i++) mat[r][i] *= sc;
    }
    __syncthreads();

    // scores: 4x8 register tile per thread, + bias + mask
    {
        const int rg = tid & 15, cg = tid >> 4;
        const int r0 = rg * 4, c0 = cg * 8;
        float acc[4][8];
        #pragma unroll
        for (int j = 0; j < 4; j++)
            #pragma unroll
            for (int l = 0; l < 8; l++) acc[j][l] = 0.0f;

        #pragma unroll
        for (int i = 0; i < 32; i++) {
            float aq[4], bk[8];
            #pragma unroll
            for (int j = 0; j < 4; j++) aq[j] = sq[r0 + j][i];
            #pragma unroll
            for (int l = 0; l < 8; l++) bk[l] = sk[c0 + l][i];
            #pragma unroll
            for (int j = 0; j < 4; j++)
                #pragma unroll
                for (int l = 0; l < 8; l++)
                    acc[j][l] = fmaf(aq[j], bk[l], acc[j][l]);
        }
        const float* mk = mask + (size_t)(b & 63) * 4096;
        const float* bi = g_bias + h * 4096;
        #pragma unroll
        for (int j = 0; j < 4; j++)
            #pragma unroll
            for (int l = 0; l < 8; l++) {
                int r = r0 + j, c = c0 + l;
                sa[r][c] = acc[j][l] + bi[r * 64 + c] + mk[r * 64 + c];
            }
    }
    __syncthreads();

    // softmax: one row per thread (threads 0..63)
    if (tid < 64) {
        float v[64];
        float m = -1e30f;
        #pragma unroll
        for (int c = 0; c < 64; c++) { v[c] = sa[tid][c]; m = fmaxf(m, v[c]); }
        float s0 = 0.f, s1 = 0.f, s2 = 0.f, s3 = 0.f;
        #pragma unroll
        for (int c = 0; c < 64; c += 4) {
            v[c + 0] = expf(v[c + 0] - m); s0 += v[c + 0];
            v[c + 1] = expf(v[c + 1] - m); s1 += v[c + 1];
            v[c + 2] = expf(v[c + 2] - m); s2 += v[c + 2];
            v[c + 3] = expf(v[c + 3] - m); s3 += v[c + 3];
        }
        float inv = 1.0f / ((s0 + s1) + (s2 + s3));
        #pragma unroll
        for (int c = 0; c < 64; c++) sa[tid][c] = v[c] * inv;
    }
    __syncthreads();

    // ctx = P @ V : 4x4 register tile per thread, write to g_ctx
    {
        const int rg = tid & 15, dg = tid >> 4;
        const int r0 = rg * 4, d0 = dg * 4;
        float acc[4][4];
        #pragma unroll
        for (int j = 0; j < 4; j++)
            #pragma unroll
            for (int l = 0; l < 4; l++) acc[j][l] = 0.0f;

        #pragma unroll
        for (int c = 0; c < 64; c++) {
            float ap[4], bv[4];
            #pragma unroll
            for (int j = 0; j < 4; j++) ap[j] = sa[r0 + j][c];
            #pragma unroll
            for (int l = 0; l < 4; l++) bv[l] = sv[c][d0 + l];
            #pragma unroll
            for (int j = 0; j < 4; j++)
                #pragma unroll
                for (int l = 0; l < 4; l++)
                    acc[j][l] = fmaf(ap[j], bv[l], acc[j][l]);
        }
        float* outp = g_ctx + (size_t)b * 64 * DIMF + h * 32;
        #pragma unroll
        for (int j = 0; j < 4; j++) {
            *(float4*)(outp + (size_t)(r0 + j) * DIMF + d0) =
                make_float4(acc[j][0], acc[j][1], acc[j][2], acc[j][3]);
        }
    }
}

// ---------------------------------------------------------------------------
extern "C" void kernel_launch(void* const* d_in, const int* in_sizes, int n_in,
                              void* d_out, int out_size)
{
    const float* x           = (const float*)d_in[0];
    const float* mask        = (const float*)d_in[1];
    const float* qkv_w       = (const float*)d_in[2];
    const float* proj_w      = (const float*)d_in[3];
    const float* proj_b      = (const float*)d_in[4];
    const float* cpb_w1      = (const float*)d_in[5];
    const float* cpb_b1      = (const float*)d_in[6];
    const float* cpb_w2      = (const float*)d_in[7];
    const float* cpb_b2      = (const float*)d_in[8];
    const float* logit_scale = (const float*)d_in[9];
    const float* rpb_table   = (const float*)d_in[10];
    const int*   rpb_idx     = (const int*)d_in[11];
    float* out = (float*)d_out;

    float *qkv_ptr = nullptr, *ctx_ptr = nullptr;
    cudaGetSymbolAddress((void**)&qkv_ptr, g_qkv);
    cudaGetSymbolAddress((void**)&ctx_ptr, g_ctx);

    // K0: CPB bias table
    rpb_kernel<<<1, 256>>>(rpb_table, cpb_w1, cpb_b1, cpb_w2, cpb_b2, rpb_idx);

    // K1: QKV GEMM  (65536x384)@(384x1152)
    sgemm128<<<dim3(QKVCOLS / 128, MTOK / 128), 256>>>(
        x, qkv_w, nullptr, qkv_ptr, MTOK, QKVCOLS, DIMF);

    // K2: attention per (head, window)
    attn_kernel<<<dim3(NHEADS, NWIN), 128>>>(mask, logit_scale);

    // K3: projection  (65536x384)@(384x384) + bias
    sgemm128<<<dim3(DIMF / 128, MTOK / 128), 256>>>(
        ctx_ptr, proj_w, proj_b, out, MTOK, DIMF, DIMF);
}

// round 5
// speedup vs baseline: 1.6783x; 1.6783x over previous
#include <cuda_runtime.h>
#include <cuda_bf16.h>
#include <math.h>
#include <cstdint>

#define NWIN   1024
#define NT     64
#define DIMF   384
#define NHEADS 12
#define HDIM   32
#define MTOK   (NWIN * NT)          // 65536
#define QKVCOLS (3 * DIMF)          // 1152
#define KSPLIT  (3 * DIMF)          // 1152 = split-3 concatenated K
#define MAX_LOGIT 4.605170185988091f // ln(100)

#define BK      32
#define ASTRIDE 40                   // 32 + 8 pad (80 bytes/row)

// ---------------------------------------------------------------------------
// Scratch (device globals)
// ---------------------------------------------------------------------------
__device__ float         g_qkv[(size_t)MTOK * QKVCOLS];     // 302 MB
__device__ float         g_ctx[(size_t)MTOK * DIMF];        // 100 MB
__device__ float         g_bias[NHEADS * NT * NT];
__device__ __nv_bfloat16 g_a[(size_t)MTOK * KSPLIT];        // 151 MB
__device__ __nv_bfloat16 g_wq[(size_t)QKVCOLS * KSPLIT];
__device__ __nv_bfloat16 g_wp[(size_t)DIMF * KSPLIT];

// ---------------------------------------------------------------------------
__device__ __forceinline__ uint32_t smem_u32(const void* p) {
    uint32_t a;
    asm("{ .reg .u64 t; cvta.to.shared.u64 t, %1; cvt.u32.u64 %0, t; }" : "=r"(a) : "l"(p));
    return a;
}
__device__ __forceinline__ void cp_async16(uint32_t saddr, const void* gaddr) {
    asm volatile("cp.async.cg.shared.global [%0], [%1], 16;" :: "r"(saddr), "l"(gaddr) : "memory");
}
__device__ __forceinline__ void ldm_x4(uint32_t& r0, uint32_t& r1, uint32_t& r2, uint32_t& r3,
                                       uint32_t addr) {
    asm volatile("ldmatrix.sync.aligned.m8n8.x4.shared.b16 {%0,%1,%2,%3}, [%4];"
                 : "=r"(r0), "=r"(r1), "=r"(r2), "=r"(r3) : "r"(addr));
}
__device__ __forceinline__ void mma16816(float& c0, float& c1, float& c2, float& c3,
                                         uint32_t a0, uint32_t a1, uint32_t a2, uint32_t a3,
                                         uint32_t b0, uint32_t b1) {
    asm volatile("mma.sync.aligned.m16n8k16.row.col.f32.bf16.bf16.f32 "
                 "{%0,%1,%2,%3}, {%4,%5,%6,%7}, {%8,%9}, {%0,%1,%2,%3};"
                 : "+f"(c0), "+f"(c1), "+f"(c2), "+f"(c3)
                 : "r"(a0), "r"(a1), "r"(a2), "r"(a3), "r"(b0), "r"(b1));
}

// ---------------------------------------------------------------------------
// K0: continuous position bias MLP + gather + 16*sigmoid
// ---------------------------------------------------------------------------
__global__ void rpb_kernel(const float* __restrict__ table,
                           const float* __restrict__ w1,
                           const float* __restrict__ b1,
                           const float* __restrict__ w2,
                           const float* __restrict__ b2,
                           const int*   __restrict__ idx)
{
    __shared__ float s_w1[1024];
    __shared__ float s_b1[512];
    __shared__ float s_w2[512 * 12];
    __shared__ float s_b2[12];
    __shared__ float s_rpb[225 * 12];
    int tid = threadIdx.x;

    for (int i = tid; i < 1024; i += 256) s_w1[i] = w1[i];
    for (int i = tid; i < 512;  i += 256) s_b1[i] = b1[i];
    for (int i = tid; i < 6144; i += 256) s_w2[i] = w2[i];
    if (tid < 12) s_b2[tid] = b2[tid];
    __syncthreads();

    if (tid < 225) {
        float t0 = table[tid * 2 + 0];
        float t1 = table[tid * 2 + 1];
        float acc[12];
        #pragma unroll
        for (int h = 0; h < 12; h++) acc[h] = s_b2[h];
        for (int j = 0; j < 512; j++) {
            float hj = fmaf(t0, s_w1[j], fmaf(t1, s_w1[512 + j], s_b1[j]));
            hj = fmaxf(hj, 0.0f);
            #pragma unroll
            for (int h = 0; h < 12; h++)
                acc[h] = fmaf(hj, s_w2[j * 12 + h], acc[h]);
        }
        #pragma unroll
        for (int h = 0; h < 12; h++) s_rpb[tid * 12 + h] = acc[h];
    }
    __syncthreads();

    for (int o = tid; o < NHEADS * NT * NT; o += 256) {
        int h = o >> 12;
        int p = o & 4095;
        float r = s_rpb[idx[p] * 12 + h];
        g_bias[o] = 16.0f / (1.0f + expf(-r));
    }
}

// ---------------------------------------------------------------------------
// Split fp32 activations [rows x 384] -> bf16 [rows x 1152] = [hi | hi | lo]
// ---------------------------------------------------------------------------
__global__ __launch_bounds__(256) void split_act(const float* __restrict__ in,
                                                 __nv_bfloat16* __restrict__ out)
{
    size_t t = (size_t)blockIdx.x * 256 + threadIdx.x;   // over MTOK*96 float4s
    if (t >= (size_t)MTOK * 96) return;
    size_t m = t / 96;
    int c = (int)(t % 96) * 4;
    float4 v = *(const float4*)(in + m * DIMF + c);

    __nv_bfloat16 h0 = __float2bfloat16(v.x), h1 = __float2bfloat16(v.y);
    __nv_bfloat16 h2 = __float2bfloat16(v.z), h3 = __float2bfloat16(v.w);
    __nv_bfloat16 l0 = __float2bfloat16(v.x - __bfloat162float(h0));
    __nv_bfloat16 l1 = __float2bfloat16(v.y - __bfloat162float(h1));
    __nv_bfloat16 l2 = __float2bfloat16(v.z - __bfloat162float(h2));
    __nv_bfloat16 l3 = __float2bfloat16(v.w - __bfloat162float(h3));

    __nv_bfloat162 hp0 = __halves2bfloat162(h0, h1), hp1 = __halves2bfloat162(h2, h3);
    __nv_bfloat162 lp0 = __halves2bfloat162(l0, l1), lp1 = __halves2bfloat162(l2, l3);

    __nv_bfloat162* o0 = (__nv_bfloat162*)(out + m * KSPLIT + c);
    __nv_bfloat162* o1 = (__nv_bfloat162*)(out + m * KSPLIT + DIMF + c);
    __nv_bfloat162* o2 = (__nv_bfloat162*)(out + m * KSPLIT + 2 * DIMF + c);
    o0[0] = hp0; o0[1] = hp1;   // hi  (pairs with w hi)
    o1[0] = hp0; o1[1] = hp1;   // hi  (pairs with w lo)
    o2[0] = lp0; o2[1] = lp1;   // lo  (pairs with w hi)
}

// ---------------------------------------------------------------------------
// Split + transpose weights [384 x Ncols] -> bf16 [Ncols x 1152] = [hi|lo|hi]
// ---------------------------------------------------------------------------
__global__ __launch_bounds__(256) void split_w(const float* __restrict__ w,
                                               __nv_bfloat16* __restrict__ out, int Ncols)
{
    int t = blockIdx.x * 256 + threadIdx.x;
    if (t >= DIMF * Ncols) return;
    int k = t / Ncols, n = t % Ncols;               // coalesced read
    float v = w[(size_t)k * Ncols + n];
    __nv_bfloat16 h = __float2bfloat16(v);
    __nv_bfloat16 l = __float2bfloat16(v - __bfloat162float(h));
    __nv_bfloat16* o = out + (size_t)n * KSPLIT;
    o[k] = h;
    o[DIMF + k] = l;
    o[2 * DIMF + k] = h;
}

// ---------------------------------------------------------------------------
// HMMA bf16 GEMM: C[M,N] = A'[M,K] @ B'[N,K]^T (+bias)
// CTA: 256 thr, tile 128x128xBK(32), double-buffered cp.async.
// Warp tile 64(M)x32(N): wm = (wid&1)*64, wn = (wid>>1)*32.
// ---------------------------------------------------------------------------
__global__ __launch_bounds__(256) void gemm_hmma(
    const __nv_bfloat16* __restrict__ A, const __nv_bfloat16* __restrict__ B,
    const float* __restrict__ bias, float* __restrict__ C, int N, int K)
{
    __shared__ __nv_bfloat16 sA[2][128 * ASTRIDE];
    __shared__ __nv_bfloat16 sB[2][128 * ASTRIDE];

    const int tid  = threadIdx.x;
    const int wid  = tid >> 5, lane = tid & 31;
    const int m0   = blockIdx.y * 128, n0 = blockIdx.x * 128;
    const int wm   = (wid & 1) * 64;
    const int wn   = (wid >> 1) * 32;
    const int KT   = K / BK;

    float c[4][4][4];
    #pragma unroll
    for (int i = 0; i < 4; i++)
        #pragma unroll
        for (int j = 0; j < 4; j++)
            #pragma unroll
            for (int l = 0; l < 4; l++) c[i][j][l] = 0.0f;

    // cp.async mapping: thread handles rows lrow and lrow+64, 16B chunk lq
    const int lrow = tid >> 2;        // 0..63
    const int lq   = tid & 3;         // 0..3 (16B chunks across 64B row)
    const __nv_bfloat16* gA0 = A + (size_t)(m0 + lrow)      * K + lq * 8;
    const __nv_bfloat16* gA1 = A + (size_t)(m0 + lrow + 64) * K + lq * 8;
    const __nv_bfloat16* gB0 = B + (size_t)(n0 + lrow)      * K + lq * 8;
    const __nv_bfloat16* gB1 = B + (size_t)(n0 + lrow + 64) * K + lq * 8;

    uint32_t sA_st[2], sB_st[2], sA_base[2], sB_base[2];
    #pragma unroll
    for (int s = 0; s < 2; s++) {
        sA_base[s] = smem_u32(&sA[s][0]);
        sB_base[s] = smem_u32(&sB[s][0]);
        sA_st[s] = sA_base[s] + (lrow * ASTRIDE + lq * 8) * 2;
        sB_st[s] = sB_base[s] + (lrow * ASTRIDE + lq * 8) * 2;
    }
    const uint32_t rowoff = 64 * ASTRIDE * 2;

    // ldmatrix source addresses (per lane), as offsets added to stage base
    // A: row = wm + mi*16 + (lane&15), col = kk + (lane>>4)*8
    const uint32_t a_off = ((wm + (lane & 15)) * ASTRIDE + (lane >> 4) * 8) * 2;
    // B: row = wn + p*16 + (lane&7) + ((lane>>4)<<3), col = kk + ((lane>>3)&1)*8
    const uint32_t b_off = ((wn + (lane & 7) + ((lane >> 4) << 3)) * ASTRIDE
                            + ((lane >> 3) & 1) * 8) * 2;

    // prologue: stage 0
    {
        cp_async16(sA_st[0],          gA0);
        cp_async16(sA_st[0] + rowoff, gA1);
        cp_async16(sB_st[0],          gB0);
        cp_async16(sB_st[0] + rowoff, gB1);
        asm volatile("cp.async.commit_group;" ::: "memory");
    }

    for (int kt = 0; kt < KT; kt++) {
        const int cur = kt & 1;
        if (kt + 1 < KT) {
            const int nxt = cur ^ 1;
            const size_t ko = (size_t)(kt + 1) * BK;
            cp_async16(sA_st[nxt],          gA0 + ko);
            cp_async16(sA_st[nxt] + rowoff, gA1 + ko);
            cp_async16(sB_st[nxt],          gB0 + ko);
            cp_async16(sB_st[nxt] + rowoff, gB1 + ko);
            asm volatile("cp.async.commit_group;" ::: "memory");
            asm volatile("cp.async.wait_group 1;" ::: "memory");
        } else {
            asm volatile("cp.async.wait_group 0;" ::: "memory");
        }
        __syncthreads();

        const uint32_t aS = sA_base[cur] + a_off;
        const uint32_t bS = sB_base[cur] + b_off;
        #pragma unroll
        for (int kk = 0; kk < 2; kk++) {      // two k16 steps per BK=32
            uint32_t a[4][4];
            #pragma unroll
            for (int mi = 0; mi < 4; mi++)
                ldm_x4(a[mi][0], a[mi][1], a[mi][2], a[mi][3],
                       aS + (mi * 16 * ASTRIDE + kk * 16) * 2);
            uint32_t b[4][2];
            #pragma unroll
            for (int p = 0; p < 2; p++) {
                uint32_t r0, r1, r2, r3;
                ldm_x4(r0, r1, r2, r3, bS + (p * 16 * ASTRIDE + kk * 16) * 2);
                b[p * 2 + 0][0] = r0; b[p * 2 + 0][1] = r1;
                b[p * 2 + 1][0] = r2; b[p * 2 + 1][1] = r3;
            }
            #pragma unroll
            for (int mi = 0; mi < 4; mi++)
                #pragma unroll
                for (int ni = 0; ni < 4; ni++)
                    mma16816(c[mi][ni][0], c[mi][ni][1], c[mi][ni][2], c[mi][ni][3],
                             a[mi][0], a[mi][1], a[mi][2], a[mi][3],
                             b[ni][0], b[ni][1]);
        }
        __syncthreads();
    }

    // epilogue
    const int g = lane >> 2, tg = lane & 3;
    #pragma unroll
    for (int ni = 0; ni < 4; ni++) {
        const int col = n0 + wn + ni * 8 + tg * 2;
        float b0 = 0.0f, b1 = 0.0f;
        if (bias) { b0 = bias[col]; b1 = bias[col + 1]; }
        #pragma unroll
        for (int mi = 0; mi < 4; mi++) {
            const int row = m0 + wm + mi * 16 + g;
            float2 v0 = make_float2(c[mi][ni][0] + b0, c[mi][ni][1] + b1);
            float2 v1 = make_float2(c[mi][ni][2] + b0, c[mi][ni][3] + b1);
            *(float2*)(C + (size_t)row * N + col)       = v0;
            *(float2*)(C + (size_t)(row + 8) * N + col) = v1;
        }
    }
}

// ---------------------------------------------------------------------------
// K2: per (head, window) cosine attention. 128 threads.
// ---------------------------------------------------------------------------
__global__ __launch_bounds__(128) void attn_kernel(
    const float* __restrict__ mask, const float* __restrict__ logit_scale)
{
    const int h   = blockIdx.x;
    const int b   = blockIdx.y;
    const int tid = threadIdx.x;

    __shared__ float sq[64][33];
    __shared__ float sk[64][33];
    __shared__ float sv[64][33];
    __shared__ float sa[64][65];
    __shared__ float s_scale;

    const float* qkv = g_qkv + (size_t)b * 64 * QKVCOLS + h * 32;

    for (int i = tid; i < 512; i += 128) {
        int row = i >> 3;
        int f   = (i & 7) * 4;
        const float* base = qkv + (size_t)row * QKVCOLS + f;
        float4 v;
        v = *(const float4*)(base);
        sq[row][f] = v.x; sq[row][f + 1] = v.y; sq[row][f + 2] = v.z; sq[row][f + 3] = v.w;
        v = *(const float4*)(base + 384);
        sk[row][f] = v.x; sk[row][f + 1] = v.y; sk[row][f + 2] = v.z; sk[row][f + 3] = v.w;
        v = *(const float4*)(base + 768);
        sv[row][f] = v.x; sv[row][f + 1] = v.y; sv[row][f + 2] = v.z; sv[row][f + 3] = v.w;
    }
    if (tid == 0) s_scale = expf(fminf(logit_scale[h], MAX_LOGIT));
    __syncthreads();

    {
        int r = tid & 63;
        float (*mat)[33] = (tid < 64) ? sq : sk;
        float ss = 0.0f;
        #pragma unroll
        for (int i = 0; i < 32; i++) { float v = mat[r][i]; ss = fmaf(v, v, ss); }
        float sc = rsqrtf(fmaxf(ss, 1e-12f));
        if (tid < 64) sc *= s_scale;
        #pragma unroll
        for (int i = 0; i < 32; i++) mat[r][i] *= sc;
    }
    __syncthreads();

    {
        const int rg = tid & 15, cg = tid >> 4;
        const int r0 = rg * 4, c0 = cg * 8;
        float acc[4][8];
        #pragma unroll
        for (int j = 0; j < 4; j++)
            #pragma unroll
            for (int l = 0; l < 8; l++) acc[j][l] = 0.0f;

        #pragma unroll
        for (int i = 0; i < 32; i++) {
            float aq[4], bk[8];
            #pragma unroll
            for (int j = 0; j < 4; j++) aq[j] = sq[r0 + j][i];
            #pragma unroll
            for (int l = 0; l < 8; l++) bk[l] = sk[c0 + l][i];
            #pragma unroll
            for (int j = 0; j < 4; j++)
                #pragma unroll
                for (int l = 0; l < 8; l++)
                    acc[j][l] = fmaf(aq[j], bk[l], acc[j][l]);
        }
        const float* mk = mask + (size_t)(b & 63) * 4096;
        const float* bi = g_bias + h * 4096;
        #pragma unroll
        for (int j = 0; j < 4; j++)
            #pragma unroll
            for (int l = 0; l < 8; l++) {
                int r = r0 + j, cc = c0 + l;
                sa[r][cc] = acc[j][l] + bi[r * 64 + cc] + mk[r * 64 + cc];
            }
    }
    __syncthreads();

    if (tid < 64) {
        float v[64];
        float m = -1e30f;
        #pragma unroll
        for (int cc = 0; cc < 64; cc++) { v[cc] = sa[tid][cc]; m = fmaxf(m, v[cc]); }
        float s0 = 0.f, s1 = 0.f, s2 = 0.f, s3 = 0.f;
        #pragma unroll
        for (int cc = 0; cc < 64; cc += 4) {
            v[cc + 0] = expf(v[cc + 0] - m); s0 += v[cc + 0];
            v[cc + 1] = expf(v[cc + 1] - m); s1 += v[cc + 1];
            v[cc + 2] = expf(v[cc + 2] - m); s2 += v[cc + 2];
            v[cc + 3] = expf(v[cc + 3] - m); s3 += v[cc + 3];
        }
        float inv = 1.0f / ((s0 + s1) + (s2 + s3));
        #pragma unroll
        for (int cc = 0; cc < 64; cc++) sa[tid][cc] = v[cc] * inv;
    }
    __syncthreads();

    {
        const int rg = tid & 15, dg = tid >> 4;
        const int r0 = rg * 4, d0 = dg * 4;
        float acc[4][4];
        #pragma unroll
        for (int j = 0; j < 4; j++)
            #pragma unroll
            for (int l = 0; l < 4; l++) acc[j][l] = 0.0f;

        #pragma unroll
        for (int cc = 0; cc < 64; cc++) {
            float ap[4], bv[4];
            #pragma unroll
            for (int j = 0; j < 4; j++) ap[j] = sa[r0 + j][cc];
            #pragma unroll
            for (int l = 0; l < 4; l++) bv[l] = sv[cc][d0 + l];
            #pragma unroll
            for (int j = 0; j < 4; j++)
                #pragma unroll
                for (int l = 0; l < 4; l++)
                    acc[j][l] = fmaf(ap[j], bv[l], acc[j][l]);
        }
        float* outp = g_ctx + (size_t)b * 64 * DIMF + h * 32;
        #pragma unroll
        for (int j = 0; j < 4; j++) {
            *(float4*)(outp + (size_t)(r0 + j) * DIMF + d0) =
                make_float4(acc[j][0], acc[j][1], acc[j][2], acc[j][3]);
        }
    }
}

// ---------------------------------------------------------------------------
extern "C" void kernel_launch(void* const* d_in, const int* in_sizes, int n_in,
                              void* d_out, int out_size)
{
    const float* x           = (const float*)d_in[0];
    const float* mask        = (const float*)d_in[1];
    const float* qkv_w       = (const float*)d_in[2];
    const float* proj_w      = (const float*)d_in[3];
    const float* proj_b      = (const float*)d_in[4];
    const float* cpb_w1      = (const float*)d_in[5];
    const float* cpb_b1      = (const float*)d_in[6];
    const float* cpb_w2      = (const float*)d_in[7];
    const float* cpb_b2      = (const float*)d_in[8];
    const float* logit_scale = (const float*)d_in[9];
    const float* rpb_table   = (const float*)d_in[10];
    const int*   rpb_idx     = (const int*)d_in[11];
    float* out = (float*)d_out;

    float *qkv_ptr = nullptr, *ctx_ptr = nullptr;
    __nv_bfloat16 *a_ptr = nullptr, *wq_ptr = nullptr, *wp_ptr = nullptr;
    cudaGetSymbolAddress((void**)&qkv_ptr, g_qkv);
    cudaGetSymbolAddress((void**)&ctx_ptr, g_ctx);
    cudaGetSymbolAddress((void**)&a_ptr,  g_a);
    cudaGetSymbolAddress((void**)&wq_ptr, g_wq);
    cudaGetSymbolAddress((void**)&wp_ptr, g_wp);

    // K0: CPB bias table + weight splits (tiny)
    rpb_kernel<<<1, 256>>>(rpb_table, cpb_w1, cpb_b1, cpb_w2, cpb_b2, rpb_idx);
    split_w<<<(DIMF * QKVCOLS + 255) / 256, 256>>>(qkv_w, wq_ptr, QKVCOLS);
    split_w<<<(DIMF * DIMF + 255) / 256, 256>>>(proj_w, wp_ptr, DIMF);

    // split activations for QKV GEMM
    split_act<<<(int)(((size_t)MTOK * 96 + 255) / 256), 256>>>(x, a_ptr);

    // K1: QKV GEMM (65536 x 1152), K'=1152, HMMA
    gemm_hmma<<<dim3(QKVCOLS / 128, MTOK / 128), 256>>>(
        a_ptr, wq_ptr, nullptr, qkv_ptr, QKVCOLS, KSPLIT);

    // K2: attention per (head, window)
    attn_kernel<<<dim3(NHEADS, NWIN), 128>>>(mask, logit_scale);

    // split ctx for proj GEMM
    split_act<<<(int)(((size_t)MTOK * 96 + 255) / 256), 256>>>(ctx_ptr, a_ptr);

    // K3: projection (65536 x 384) + bias, HMMA
    gemm_hmma<<<dim3(DIMF / 128, MTOK / 128), 256>>>(
        a_ptr, wp_ptr, proj_b, out, DIMF, KSPLIT);
}